// round 1
// baseline (speedup 1.0000x reference)
#include <cuda_runtime.h>

#define BATCH   16
#define NROWS   25200
#define NCOLS   85
#define MAXDET  300
#define CTHRES  0.25f
#define NTHREADS 1024

__global__ __launch_bounds__(NTHREADS, 1)
void compact_kernel(const float* __restrict__ pred, float* __restrict__ out)
{
    __shared__ int s_order[MAXDET];
    __shared__ int s_warp_cnt[32];
    __shared__ int s_warp_off[32];
    __shared__ int s_base;
    __shared__ int s_total;

    const int b    = blockIdx.x;
    const int tid  = threadIdx.x;
    const int lane = tid & 31;
    const int warp = tid >> 5;

    const float* bpred = pred + (long long)b * NROWS * NCOLS;

    if (tid == 0) s_base = 0;
    __syncthreads();

    const int nchunks = (NROWS + NTHREADS - 1) / NTHREADS;  // 25

    for (int c = 0; c < nchunks; ++c) {
        int i = c * NTHREADS + tid;
        bool m = false;
        if (i < NROWS) {
            float conf = bpred[(long long)i * NCOLS + 4];
            m = conf > CTHRES;
        }
        unsigned bal = __ballot_sync(0xffffffffu, m);
        int wprefix = __popc(bal & ((1u << lane) - 1u));
        if (lane == 0) s_warp_cnt[warp] = __popc(bal);
        __syncthreads();

        if (warp == 0) {
            int v = s_warp_cnt[lane];
            int inc = v;
            #pragma unroll
            for (int o = 1; o < 32; o <<= 1) {
                int u = __shfl_up_sync(0xffffffffu, inc, o);
                if (lane >= o) inc += u;
            }
            s_warp_off[lane] = inc - v;   // exclusive prefix of warp counts
            if (lane == 31) s_total = inc;
        }
        __syncthreads();

        int base = s_base;                 // read before update
        int rank = base + s_warp_off[warp] + wprefix;
        if (m && rank < MAXDET) s_order[rank] = i;
        __syncthreads();

        if (tid == 0) s_base = base + s_total;
        __syncthreads();

        if (s_base >= MAXDET) break;       // uniform: no later row can rank < 300
    }
    __syncthreads();

    int cnt = s_base;
    if (cnt > MAXDET) cnt = MAXDET;

    float* bout = out + (long long)b * MAXDET * NCOLS;

    // Gather: 300*85 = 25500 elements, coalesced stores, independent loads.
    #pragma unroll 5
    for (int e = tid; e < MAXDET * NCOLS; e += NTHREADS) {
        int slot = e / NCOLS;
        int col  = e - slot * NCOLS;
        float v = 0.0f;
        if (slot < cnt) {
            int src = s_order[slot];
            v = bpred[(long long)src * NCOLS + col];
        }
        bout[e] = v;
    }
}

extern "C" void kernel_launch(void* const* d_in, const int* in_sizes, int n_in,
                              void* d_out, int out_size)
{
    const float* pred = (const float*)d_in[0];
    float* out = (float*)d_out;
    compact_kernel<<<BATCH, NTHREADS>>>(pred, out);
}

// round 2
// speedup vs baseline: 1.6570x; 1.6570x over previous
#include <cuda_runtime.h>

#define BATCH    16
#define NROWS    25200
#define NCOLS    85
#define MAXDET   300
#define CTHRES   0.25f
#define NTHREADS 256
#define SLICES   20            // CTAs per image
#define SLOTS    (MAXDET / SLICES)   // 15 slots per CTA

__global__ __launch_bounds__(NTHREADS, 4)
void compact_kernel(const float* __restrict__ pred, float* __restrict__ out)
{
    __shared__ int s_order[MAXDET];
    __shared__ int s_warp_cnt[NTHREADS / 32];
    __shared__ int s_warp_off[NTHREADS / 32];
    __shared__ int s_base;
    __shared__ int s_total;

    const int b     = blockIdx.x / SLICES;       // image
    const int slice = blockIdx.x % SLICES;       // slot slice within image
    const int tid   = threadIdx.x;
    const int lane  = tid & 31;
    const int warp  = tid >> 5;

    const int slice_lo = slice * SLOTS;
    const int slice_hi = slice_lo + SLOTS;

    const float* bpred = pred + (long long)b * NROWS * NCOLS;

    if (tid == 0) s_base = 0;
    __syncthreads();

    const int nchunks = (NROWS + NTHREADS - 1) / NTHREADS;  // 99

    for (int c = 0; c < nchunks; ++c) {
        int i = c * NTHREADS + tid;
        bool m = false;
        if (i < NROWS) {
            float conf = bpred[(long long)i * NCOLS + 4];
            m = conf > CTHRES;
        }
        unsigned bal = __ballot_sync(0xffffffffu, m);
        int wprefix = __popc(bal & ((1u << lane) - 1u));
        if (lane == 0) s_warp_cnt[warp] = __popc(bal);
        __syncthreads();

        if (warp == 0) {
            int v = (lane < NTHREADS / 32) ? s_warp_cnt[lane] : 0;
            int inc = v;
            #pragma unroll
            for (int o = 1; o < 32; o <<= 1) {
                int u = __shfl_up_sync(0xffffffffu, inc, o);
                if (lane >= o) inc += u;
            }
            if (lane < NTHREADS / 32) s_warp_off[lane] = inc - v;
            if (lane == 31) s_total = inc;
        }
        __syncthreads();

        int base = s_base;
        int rank = base + s_warp_off[warp] + wprefix;
        if (m && rank < MAXDET) s_order[rank] = i;
        __syncthreads();

        if (tid == 0) s_base = base + s_total;
        __syncthreads();

        // This CTA only needs ranks < slice_hi resolved; once the running
        // count passes slice_hi, later rows cannot affect our slots.
        if (s_base >= slice_hi) break;
    }
    __syncthreads();

    int cnt = s_base;                    // total passing seen (stable prefix)
    if (cnt > MAXDET) cnt = MAXDET;

    float* bout = out + (long long)b * MAXDET * NCOLS + (long long)slice_lo * NCOLS;

    // Gather this CTA's slice: SLOTS*NCOLS = 1275 elements, coalesced stores.
    #pragma unroll
    for (int e = tid; e < SLOTS * NCOLS; e += NTHREADS) {
        int slot_local = e / NCOLS;
        int col        = e - slot_local * NCOLS;
        int slot       = slice_lo + slot_local;
        float v = 0.0f;
        if (slot < cnt) {
            int src = s_order[slot];
            v = bpred[(long long)src * NCOLS + col];
        }
        bout[e] = v;
    }
}

extern "C" void kernel_launch(void* const* d_in, const int* in_sizes, int n_in,
                              void* d_out, int out_size)
{
    const float* pred = (const float*)d_in[0];
    float* out = (float*)d_out;
    compact_kernel<<<BATCH * SLICES, NTHREADS>>>(pred, out);
}